// round 12
// baseline (speedup 1.0000x reference)
#include <cuda_runtime.h>
#include <cuda_bf16.h>
#include <cuda_fp8.h>
#include <cstdint>
#include <cstddef>

#define FP8_MAX 448.0f

// ---------------- scratch (device globals; no runtime allocation) -------------
static __device__ __align__(16) uint8_t g_x_fp8[(size_t)32768 * 1024];
static __device__ __align__(16) uint8_t g_w_fp8[(size_t)1024 * 1024];
static __device__ float g_part[1024];
static __device__ float g_amax;

__device__ __forceinline__ float bf16r(float v) {
    return __bfloat162float(__float2bfloat16(v));
}

// ---------------- PTX helpers -------------------------------------------------
__device__ __forceinline__ uint32_t smem_u32(const void* p) {
    uint32_t a;
    asm("{ .reg .u64 t; cvta.to.shared.u64 t, %1; cvt.u32.u64 %0, t; }"
        : "=r"(a) : "l"(p));
    return a;
}
__device__ __forceinline__ void cp_async16(uint32_t dst, const void* src) {
    asm volatile("cp.async.cg.shared.global [%0], [%1], 16;\n" :: "r"(dst), "l"(src));
}
__device__ __forceinline__ void cp_commit() {
    asm volatile("cp.async.commit_group;\n" ::: "memory");
}
template <int N>
__device__ __forceinline__ void cp_wait() {
    asm volatile("cp.async.wait_group %0;\n" :: "n"(N) : "memory");
}
__device__ __forceinline__ void ldmatrix_x4(uint32_t* r, uint32_t addr) {
    asm volatile("ldmatrix.sync.aligned.m8n8.x4.shared.b16 {%0,%1,%2,%3}, [%4];"
                 : "=r"(r[0]), "=r"(r[1]), "=r"(r[2]), "=r"(r[3]) : "r"(addr));
}
// fp8 e4m3 MMA: D(16x8,f32) += A(16x32,e4m3) * B(32x8,e4m3)
__device__ __forceinline__ void mma_fp8(float* c, const uint32_t* a, const uint32_t* b) {
    asm volatile(
        "mma.sync.aligned.m16n8k32.row.col.f32.e4m3.e4m3.f32 "
        "{%0,%1,%2,%3}, {%4,%5,%6,%7}, {%8,%9}, {%0,%1,%2,%3};"
        : "+f"(c[0]), "+f"(c[1]), "+f"(c[2]), "+f"(c[3])
        : "r"(a[0]), "r"(a[1]), "r"(a[2]), "r"(a[3]), "r"(b[0]), "r"(b[1]));
}

// ---------------- deterministic two-pass amax -----------------------------------
__global__ void k_amax1(const float* __restrict__ x, int n) {
    __shared__ float sm[256];
    float m0 = 0.0f, m1 = 0.0f;
    const float4* x4 = (const float4*)x;
    int n4 = n >> 2;
    int stride = gridDim.x * blockDim.x;
    for (int j = blockIdx.x * blockDim.x + threadIdx.x; j < n4; j += stride) {
        float4 v = x4[j];
        m0 = fmaxf(m0, fmaxf(fabsf(bf16r(v.x)), fabsf(bf16r(v.y))));
        m1 = fmaxf(m1, fmaxf(fabsf(bf16r(v.z)), fabsf(bf16r(v.w))));
    }
    sm[threadIdx.x] = fmaxf(m0, m1);
    __syncthreads();
#pragma unroll
    for (int o = 128; o > 0; o >>= 1) {
        if (threadIdx.x < o) sm[threadIdx.x] = fmaxf(sm[threadIdx.x], sm[threadIdx.x + o]);
        __syncthreads();
    }
    if (threadIdx.x == 0) g_part[blockIdx.x] = sm[0];
}
__global__ void k_amax2() {
    __shared__ float sm[1024];
    sm[threadIdx.x] = g_part[threadIdx.x];
    __syncthreads();
#pragma unroll
    for (int o = 512; o > 0; o >>= 1) {
        if (threadIdx.x < o) sm[threadIdx.x] = fmaxf(sm[threadIdx.x], sm[threadIdx.x + o]);
        __syncthreads();
    }
    if (threadIdx.x == 0) g_amax = fmaxf(sm[0], 1e-12f);
}

// ---------------- staging quant (x and w in one launch) --------------------------
__global__ void k_quant(const float* __restrict__ x, int nx4,
                        const float* __restrict__ w, int nw4) {
    float s = g_amax / FP8_MAX;
    int i = blockIdx.x * blockDim.x + threadIdx.x;
    int stride = gridDim.x * blockDim.x;
    const float4* x4 = (const float4*)x;
    uchar4* dx = (uchar4*)g_x_fp8;
    for (int j = i; j < nx4; j += stride) {
        float4 v = x4[j];
        uchar4 q;
        q.x = __nv_fp8_e4m3(bf16r(v.x) / s).__x;
        q.y = __nv_fp8_e4m3(bf16r(v.y) / s).__x;
        q.z = __nv_fp8_e4m3(bf16r(v.z) / s).__x;
        q.w = __nv_fp8_e4m3(bf16r(v.w) / s).__x;
        dx[j] = q;
    }
    const float4* w4 = (const float4*)w;
    uchar4* dw = (uchar4*)g_w_fp8;
    for (int j = i; j < nw4; j += stride) {
        float4 v = w4[j];
        uchar4 q;
        q.x = __nv_fp8_e4m3(v.x).__x;
        q.y = __nv_fp8_e4m3(v.y).__x;
        q.z = __nv_fp8_e4m3(v.z).__x;
        q.w = __nv_fp8_e4m3(v.w).__x;
        dw[j] = q;
    }
}

// ---- fp8 MMA GEMM: 128x128 tile, fragment double-buffering, 4-stage cp.async ---
#define BM 128
#define BN 128
#define BK 32                            // 32 fp8 bytes of K per stage
#define ROWB 48                          // 32 data + 16 pad (16B aligned rows)
#define OPB (128 * ROWB)                 // 6144 per operand tile
#define STB (2 * OPB)                    // 12288 per stage
#define STAGES 4
#define SMEM_GEMM_TOTAL (STAGES * STB)   // 49152 == default 48KB

__global__ void __launch_bounds__(256, 2)   // <=128 regs, 2 CTAs/SM, 1 wave
k_gemm(const float* __restrict__ wscale,
       const float* __restrict__ bias,
       float* __restrict__ out,          // f32 container, bf16-rounded values
       int M, int N, int K)
{
    extern __shared__ __align__(128) uint8_t smem[];
    const uint32_t sbase = smem_u32(smem);
    const int tid = threadIdx.x;
    const int wid = tid >> 5;
    const int lane = tid & 31;
    const int g = lane >> 2;             // groupID
    const int t = lane & 3;              // threadID_in_group
    const int wm = (wid & 3) * 32;       // 4 warps along M, 32 rows each
    const int wn = (wid >> 2) * 64;      // 2 warps along N, 64 cols each
    const int m0 = blockIdx.y * BM;
    const int n0 = blockIdx.x * BN;
    const int NK = K / BK;               // 32 (even)

    // ldmatrix lane offsets (validated fragment maps)
    const uint32_t la0 = (uint32_t)((wm + (lane & 15)) * ROWB + (lane >> 4) * 16);
    const uint32_t la1 = la0 + 16u * ROWB;
    const uint32_t bo = (uint32_t)(
        (wn + (lane & 7) + ((lane & 16) >> 1)) * ROWB + ((lane & 8) ? 16 : 0));

    // producer: 2 operands x 128 rows x 1 16B piece each -> 256 threads x2
    const int prow = tid >> 1;
    const uint32_t apo = (uint32_t)(prow * ROWB + (tid & 1) * 16);
    const uint8_t* a_ptr = g_x_fp8 + (size_t)(m0 + prow) * K + (tid & 1) * 16;
    const uint8_t* b_ptr = g_w_fp8 + (size_t)(n0 + prow) * K + (tid & 1) * 16;

    auto load_chunk = [&](int kt, int st) {
        uint32_t base = sbase + (uint32_t)st * STB;
        cp_async16(base + apo, a_ptr + (size_t)kt * BK);
        cp_async16(base + OPB + apo, b_ptr + (size_t)kt * BK);
    };

    float c[2][8][4];
#pragma unroll
    for (int i = 0; i < 2; i++)
#pragma unroll
        for (int j = 0; j < 8; j++)
#pragma unroll
            for (int q = 0; q < 4; q++) c[i][j][q] = 0.0f;

    // fragment double buffers
    uint32_t af0[2][4], bf0[4][4], af1[2][4], bf1[4][4];

    // prologue: chunks 0,1,2 in flight; frags of chunk 0 into set 0
#pragma unroll
    for (int s = 0; s < 3; s++) {
        load_chunk(s, s);
        cp_commit();
    }
    cp_wait<1>();                        // chunks 0,1 resident
    __syncthreads();
    {
        uint32_t b0 = sbase;             // stage 0
        ldmatrix_x4(af0[0], b0 + la0);
        ldmatrix_x4(af0[1], b0 + la1);
#pragma unroll
        for (int j = 0; j < 4; j++)
            ldmatrix_x4(bf0[j], b0 + OPB + bo + (uint32_t)(j * 16 * ROWB));
    }

    auto step = [&](int i, uint32_t (&afc)[2][4], uint32_t (&bfc)[4][4],
                    uint32_t (&afn)[2][4], uint32_t (&bfn)[4][4]) {
        if (i + 3 < NK) load_chunk(i + 3, (i + 3) & 3);
        cp_commit();                     // unconditional: keeps wait counts valid
        if (i + 1 < NK) {
            cp_wait<2>();                // chunk i+1 resident
            uint32_t nb = sbase + (uint32_t)((i + 1) & 3) * STB;
            ldmatrix_x4(afn[0], nb + la0);
            ldmatrix_x4(afn[1], nb + la1);
#pragma unroll
            for (int j = 0; j < 4; j++)
                ldmatrix_x4(bfn[j], nb + OPB + bo + (uint32_t)(j * 16 * ROWB));
        } else {
            cp_wait<0>();
        }
        // dense MMA burst for chunk i (frags already in registers)
#pragma unroll
        for (int ti = 0; ti < 2; ti++)
#pragma unroll
            for (int j = 0; j < 4; j++) {
                mma_fp8(c[ti][2 * j],     afc[ti], &bfc[j][0]);
                mma_fp8(c[ti][2 * j + 1], afc[ti], &bfc[j][2]);
            }
        __syncthreads();                 // buffer (i+3)&3 safe to refill next iters
    };

    for (int i = 0; i < NK; i += 2) {
        step(i,     af0, bf0, af1, bf1);
        step(i + 1, af1, bf1, af0, bf0);
    }

    // epilogue: f32 out, values rounded to bf16 grid (matches .astype(bf16))
    float act_scale = g_amax / FP8_MAX;
    const int row_b = m0 + wm + g;
    const int col_b = wn + 2 * t;
#pragma unroll
    for (int ti = 0; ti < 2; ti++) {
#pragma unroll
        for (int tj = 0; tj < 8; tj++) {
            int col = n0 + col_b + 8 * tj;
            float s0 = act_scale * __ldg(&wscale[col]);
            float s1 = act_scale * __ldg(&wscale[col + 1]);
            float b0 = __ldg(&bias[col]);
            float b1 = __ldg(&bias[col + 1]);
            int r0 = row_b + 16 * ti;
            int r1 = r0 + 8;
            float2 h0 = make_float2(bf16r(fmaf(c[ti][tj][0], s0, b0)),
                                    bf16r(fmaf(c[ti][tj][1], s1, b1)));
            float2 h1 = make_float2(bf16r(fmaf(c[ti][tj][2], s0, b0)),
                                    bf16r(fmaf(c[ti][tj][3], s1, b1)));
            *(float2*)(out + (size_t)r0 * N + col) = h0;
            *(float2*)(out + (size_t)r1 * N + col) = h1;
        }
    }
}

// ---------------- launch --------------------------------------------------------
extern "C" void kernel_launch(void* const* d_in, const int* in_sizes, int n_in,
                              void* d_out, int out_size) {
    const float* x  = (const float*)d_in[0];
    const float* w  = (const float*)d_in[1];
    const float* ws = (const float*)d_in[2];
    const float* b  = (const float*)d_in[3];
    float* out = (float*)d_out;                  // f32 container (numpy has no bf16)

    int d_out_dim = in_sizes[2];                 // 1024
    int d_in_dim  = in_sizes[1] / d_out_dim;     // 1024
    int tokens    = in_sizes[0] / d_in_dim;      // 32768
    int nx = in_sizes[0];
    int nw = in_sizes[1];

    k_amax1<<<1024, 256>>>(x, nx);
    k_amax2<<<1, 1024>>>();
    k_quant<<<2048, 256>>>(x, nx >> 2, w, nw >> 2);

    dim3 grid(d_out_dim / BN, tokens / BM);      // N-tiles fastest -> A-tile L2 reuse
    k_gemm<<<grid, 256, SMEM_GEMM_TOTAL>>>(ws, b, out, tokens, d_out_dim, d_in_dim);
}

// round 13
// speedup vs baseline: 2.2193x; 2.2193x over previous
#include <cuda_runtime.h>
#include <cuda_bf16.h>
#include <cuda_fp8.h>
#include <cstdint>
#include <cstddef>

#define FP8_MAX 448.0f

// ---------------- scratch (device globals; no runtime allocation) -------------
static __device__ __align__(16) uint8_t g_x_fp8[(size_t)32768 * 1024];
static __device__ __align__(16) uint8_t g_w_fp8[(size_t)1024 * 1024];
static __device__ float g_part[1024];
static __device__ float g_amax;

__device__ __forceinline__ float bf16r(float v) {
    return __bfloat162float(__float2bfloat16(v));
}

// ---------------- PTX helpers -------------------------------------------------
__device__ __forceinline__ uint32_t smem_u32(const void* p) {
    uint32_t a;
    asm("{ .reg .u64 t; cvta.to.shared.u64 t, %1; cvt.u32.u64 %0, t; }"
        : "=r"(a) : "l"(p));
    return a;
}
__device__ __forceinline__ void cp_async16(uint32_t dst, const void* src) {
    asm volatile("cp.async.cg.shared.global [%0], [%1], 16;\n" :: "r"(dst), "l"(src));
}
__device__ __forceinline__ void cp_commit() {
    asm volatile("cp.async.commit_group;\n" ::: "memory");
}
template <int N>
__device__ __forceinline__ void cp_wait() {
    asm volatile("cp.async.wait_group %0;\n" :: "n"(N) : "memory");
}
__device__ __forceinline__ void ldmatrix_x4(uint32_t* r, uint32_t addr) {
    asm volatile("ldmatrix.sync.aligned.m8n8.x4.shared.b16 {%0,%1,%2,%3}, [%4];"
                 : "=r"(r[0]), "=r"(r[1]), "=r"(r[2]), "=r"(r[3]) : "r"(addr));
}
// fp8 e4m3 MMA: D(16x8,f32) += A(16x32,e4m3) * B(32x8,e4m3)
__device__ __forceinline__ void mma_fp8(float* c, const uint32_t* a, const uint32_t* b) {
    asm volatile(
        "mma.sync.aligned.m16n8k32.row.col.f32.e4m3.e4m3.f32 "
        "{%0,%1,%2,%3}, {%4,%5,%6,%7}, {%8,%9}, {%0,%1,%2,%3};"
        : "+f"(c[0]), "+f"(c[1]), "+f"(c[2]), "+f"(c[3])
        : "r"(a[0]), "r"(a[1]), "r"(a[2]), "r"(a[3]), "r"(b[0]), "r"(b[1]));
}

// ---------------- deterministic two-pass amax -----------------------------------
__global__ void k_amax1(const float* __restrict__ x, int n) {
    __shared__ float sm[256];
    float m0 = 0.0f, m1 = 0.0f;
    const float4* x4 = (const float4*)x;
    int n4 = n >> 2;
    int stride = gridDim.x * blockDim.x;
    for (int j = blockIdx.x * blockDim.x + threadIdx.x; j < n4; j += stride) {
        float4 v = x4[j];
        m0 = fmaxf(m0, fmaxf(fabsf(bf16r(v.x)), fabsf(bf16r(v.y))));
        m1 = fmaxf(m1, fmaxf(fabsf(bf16r(v.z)), fabsf(bf16r(v.w))));
    }
    sm[threadIdx.x] = fmaxf(m0, m1);
    __syncthreads();
#pragma unroll
    for (int o = 128; o > 0; o >>= 1) {
        if (threadIdx.x < o) sm[threadIdx.x] = fmaxf(sm[threadIdx.x], sm[threadIdx.x + o]);
        __syncthreads();
    }
    if (threadIdx.x == 0) g_part[blockIdx.x] = sm[0];
}
__global__ void k_amax2() {
    __shared__ float sm[1024];
    sm[threadIdx.x] = g_part[threadIdx.x];
    __syncthreads();
#pragma unroll
    for (int o = 512; o > 0; o >>= 1) {
        if (threadIdx.x < o) sm[threadIdx.x] = fmaxf(sm[threadIdx.x], sm[threadIdx.x + o]);
        __syncthreads();
    }
    if (threadIdx.x == 0) g_amax = fmaxf(sm[0], 1e-12f);
}

// ---------------- staging quant (x and w in one launch) --------------------------
__global__ void k_quant(const float* __restrict__ x, int nx4,
                        const float* __restrict__ w, int nw4) {
    float s = g_amax / FP8_MAX;
    int i = blockIdx.x * blockDim.x + threadIdx.x;
    int stride = gridDim.x * blockDim.x;
    const float4* x4 = (const float4*)x;
    uchar4* dx = (uchar4*)g_x_fp8;
    for (int j = i; j < nx4; j += stride) {
        float4 v = x4[j];
        uchar4 q;
        q.x = __nv_fp8_e4m3(bf16r(v.x) / s).__x;
        q.y = __nv_fp8_e4m3(bf16r(v.y) / s).__x;
        q.z = __nv_fp8_e4m3(bf16r(v.z) / s).__x;
        q.w = __nv_fp8_e4m3(bf16r(v.w) / s).__x;
        dx[j] = q;
    }
    const float4* w4 = (const float4*)w;
    uchar4* dw = (uchar4*)g_w_fp8;
    for (int j = i; j < nw4; j += stride) {
        float4 v = w4[j];
        uchar4 q;
        q.x = __nv_fp8_e4m3(v.x).__x;
        q.y = __nv_fp8_e4m3(v.y).__x;
        q.z = __nv_fp8_e4m3(v.z).__x;
        q.w = __nv_fp8_e4m3(v.w).__x;
        dw[j] = q;
    }
}

// ---- fp8 MMA GEMM (R9 structure): BK=32, 6 stages, barrier every 2 iters -------
#define BM 128
#define BN 128
#define BK 32                            // 32 fp8 bytes of K per stage
#define ROWB 48                          // 32 data + 16 pad (16B aligned rows)
#define OPB (128 * ROWB)                 // 6144 per operand tile
#define STB (2 * OPB)                    // 12288 per stage
#define STAGES 6
#define SMEM_GEMM_TOTAL (STAGES * STB)   // 73728 (needs attribute)

__global__ void __launch_bounds__(256, 2)   // <=128 regs -> 2 CTAs/SM, 1 wave
k_gemm(const float* __restrict__ wscale,
       const float* __restrict__ bias,
       float* __restrict__ out,          // f32 container, bf16-rounded values
       int M, int N, int K)
{
    extern __shared__ __align__(128) uint8_t smem[];
    const uint32_t sbase = smem_u32(smem);
    const int tid = threadIdx.x;
    const int wid = tid >> 5;
    const int lane = tid & 31;
    const int g = lane >> 2;             // groupID
    const int t = lane & 3;              // threadID_in_group
    const int wm = (wid & 3) * 32;       // 4 warps along M
    const int wn = (wid >> 2) * 64;      // 2 warps along N (warp tile 32x64)
    const int m0 = blockIdx.y * BM;
    const int n0 = blockIdx.x * BN;
    const int NK = K / BK;               // 32

    // ldmatrix lane offsets (validated fragment maps)
    const uint32_t la0 = (uint32_t)((wm + (lane & 15)) * ROWB + (lane >> 4) * 16);
    const uint32_t la1 = la0 + 16u * ROWB;
    const uint32_t bo = (uint32_t)(
        (wn + (lane & 7) + ((lane & 16) >> 1)) * ROWB + ((lane & 8) ? 16 : 0));

    // producer: each thread 1 16B piece of A + 1 of B per chunk
    const int prow = tid >> 1;
    const uint32_t apo = (uint32_t)(prow * ROWB + (tid & 1) * 16);
    const uint8_t* a_ptr = g_x_fp8 + (size_t)(m0 + prow) * K + (tid & 1) * 16;
    const uint8_t* b_ptr = g_w_fp8 + (size_t)(n0 + prow) * K + (tid & 1) * 16;

    auto load_chunk = [&](int kt, int st) {
        uint32_t base = sbase + (uint32_t)st * STB;
        cp_async16(base + apo, a_ptr + (size_t)kt * BK);
        cp_async16(base + OPB + apo, b_ptr + (size_t)kt * BK);
    };

    float c[2][8][4];
#pragma unroll
    for (int i = 0; i < 2; i++)
#pragma unroll
        for (int j = 0; j < 8; j++)
#pragma unroll
            for (int q = 0; q < 4; q++) c[i][j][q] = 0.0f;

    // prologue: 4 chunks in flight (stages 0..3)
#pragma unroll
    for (int s = 0; s < 4; s++) {
        load_chunk(s, s);
        cp_commit();
    }

    int sr = 0, sw = 4;                  // read / write stage cursors (mod 6)
    for (int i = 0; i < NK; i++) {
        cp_wait<3>();                    // chunk i resident (i+1..i+3 in flight)
        if ((i & 1) == 0) __syncthreads();  // protects stages read at i-2, i-1

        if (i + 4 < NK) load_chunk(i + 4, sw);   // targets stage read at iter i-2
        cp_commit();                     // unconditional: keeps wait counts valid
        if (++sw == STAGES) sw = 0;

        uint32_t abase = sbase + (uint32_t)sr * STB;
        uint32_t bbase = abase + OPB;
        if (++sr == STAGES) sr = 0;

        uint32_t af[2][4];
        ldmatrix_x4(af[0], abase + la0);
        ldmatrix_x4(af[1], abase + la1);
        uint32_t bf[4][4];
#pragma unroll
        for (int j = 0; j < 4; j++)
            ldmatrix_x4(bf[j], bbase + bo + (uint32_t)(j * 16 * ROWB));

#pragma unroll
        for (int ti = 0; ti < 2; ti++)
#pragma unroll
            for (int j = 0; j < 4; j++) {
                mma_fp8(c[ti][2 * j],     af[ti], &bf[j][0]);
                mma_fp8(c[ti][2 * j + 1], af[ti], &bf[j][2]);
            }
    }

    // epilogue: f32 out, values rounded to bf16 grid (matches .astype(bf16))
    float act_scale = g_amax / FP8_MAX;
    const int row_b = m0 + wm + g;
    const int col_b = wn + 2 * t;
#pragma unroll
    for (int ti = 0; ti < 2; ti++) {
#pragma unroll
        for (int tj = 0; tj < 8; tj++) {
            int col = n0 + col_b + 8 * tj;
            float s0 = act_scale * __ldg(&wscale[col]);
            float s1 = act_scale * __ldg(&wscale[col + 1]);
            float b0 = __ldg(&bias[col]);
            float b1 = __ldg(&bias[col + 1]);
            int r0 = row_b + 16 * ti;
            int r1 = r0 + 8;
            float2 h0 = make_float2(bf16r(fmaf(c[ti][tj][0], s0, b0)),
                                    bf16r(fmaf(c[ti][tj][1], s1, b1)));
            float2 h1 = make_float2(bf16r(fmaf(c[ti][tj][2], s0, b0)),
                                    bf16r(fmaf(c[ti][tj][3], s1, b1)));
            *(float2*)(out + (size_t)r0 * N + col) = h0;
            *(float2*)(out + (size_t)r1 * N + col) = h1;
        }
    }
}

// ---------------- launch --------------------------------------------------------
extern "C" void kernel_launch(void* const* d_in, const int* in_sizes, int n_in,
                              void* d_out, int out_size) {
    const float* x  = (const float*)d_in[0];
    const float* w  = (const float*)d_in[1];
    const float* ws = (const float*)d_in[2];
    const float* b  = (const float*)d_in[3];
    float* out = (float*)d_out;                  // f32 container (numpy has no bf16)

    int d_out_dim = in_sizes[2];                 // 1024
    int d_in_dim  = in_sizes[1] / d_out_dim;     // 1024
    int tokens    = in_sizes[0] / d_in_dim;      // 32768
    int nx = in_sizes[0];
    int nw = in_sizes[1];

    // non-stream API, idempotent, legal during capture (R10-verified)
    cudaFuncSetAttribute(k_gemm, cudaFuncAttributeMaxDynamicSharedMemorySize,
                         SMEM_GEMM_TOTAL);

    k_amax1<<<1024, 256>>>(x, nx);
    k_amax2<<<1, 1024>>>();
    k_quant<<<2048, 256>>>(x, nx >> 2, w, nw >> 2);

    dim3 grid(d_out_dim / BN, tokens / BM);      // N-tiles fastest -> A-tile L2 reuse
    k_gemm<<<grid, 256, SMEM_GEMM_TOTAL>>>(ws, b, out, tokens, d_out_dim, d_in_dim);
}

// round 14
// speedup vs baseline: 2.2365x; 1.0077x over previous
#include <cuda_runtime.h>
#include <cuda_bf16.h>
#include <cuda_fp8.h>
#include <cstdint>
#include <cstddef>

#define FP8_MAX 448.0f

// ---------------- scratch (device globals; no runtime allocation) -------------
static __device__ __align__(16) uint8_t g_x_fp8[(size_t)32768 * 1024];
static __device__ __align__(16) uint8_t g_w_fp8[(size_t)1024 * 1024];
static __device__ float g_part[1024];
static __device__ float g_amax;

__device__ __forceinline__ float bf16r(float v) {
    return __bfloat162float(__float2bfloat16(v));
}

// ---------------- PTX helpers -------------------------------------------------
__device__ __forceinline__ uint32_t smem_u32(const void* p) {
    uint32_t a;
    asm("{ .reg .u64 t; cvta.to.shared.u64 t, %1; cvt.u32.u64 %0, t; }"
        : "=r"(a) : "l"(p));
    return a;
}
__device__ __forceinline__ void cp_async16(uint32_t dst, const void* src) {
    asm volatile("cp.async.cg.shared.global [%0], [%1], 16;\n" :: "r"(dst), "l"(src));
}
__device__ __forceinline__ void cp_commit() {
    asm volatile("cp.async.commit_group;\n" ::: "memory");
}
template <int N>
__device__ __forceinline__ void cp_wait() {
    asm volatile("cp.async.wait_group %0;\n" :: "n"(N) : "memory");
}
__device__ __forceinline__ void ldmatrix_x4(uint32_t* r, uint32_t addr) {
    asm volatile("ldmatrix.sync.aligned.m8n8.x4.shared.b16 {%0,%1,%2,%3}, [%4];"
                 : "=r"(r[0]), "=r"(r[1]), "=r"(r[2]), "=r"(r[3]) : "r"(addr));
}
// fp8 e4m3 MMA: D(16x8,f32) += A(16x32,e4m3) * B(32x8,e4m3)
__device__ __forceinline__ void mma_fp8(float* c, const uint32_t* a, const uint32_t* b) {
    asm volatile(
        "mma.sync.aligned.m16n8k32.row.col.f32.e4m3.e4m3.f32 "
        "{%0,%1,%2,%3}, {%4,%5,%6,%7}, {%8,%9}, {%0,%1,%2,%3};"
        : "+f"(c[0]), "+f"(c[1]), "+f"(c[2]), "+f"(c[3])
        : "r"(a[0]), "r"(a[1]), "r"(a[2]), "r"(a[3]), "r"(b[0]), "r"(b[1]));
}

// ---------------- deterministic two-pass amax -----------------------------------
__global__ void k_amax1(const float* __restrict__ x, int n) {
    __shared__ float sm[256];
    float m0 = 0.0f, m1 = 0.0f;
    const float4* x4 = (const float4*)x;
    int n4 = n >> 2;
    int stride = gridDim.x * blockDim.x;
    for (int j = blockIdx.x * blockDim.x + threadIdx.x; j < n4; j += stride) {
        float4 v = x4[j];
        m0 = fmaxf(m0, fmaxf(fabsf(bf16r(v.x)), fabsf(bf16r(v.y))));
        m1 = fmaxf(m1, fmaxf(fabsf(bf16r(v.z)), fabsf(bf16r(v.w))));
    }
    sm[threadIdx.x] = fmaxf(m0, m1);
    __syncthreads();
#pragma unroll
    for (int o = 128; o > 0; o >>= 1) {
        if (threadIdx.x < o) sm[threadIdx.x] = fmaxf(sm[threadIdx.x], sm[threadIdx.x + o]);
        __syncthreads();
    }
    if (threadIdx.x == 0) g_part[blockIdx.x] = sm[0];
}
__global__ void k_amax2() {
    __shared__ float sm[1024];
    sm[threadIdx.x] = g_part[threadIdx.x];
    __syncthreads();
#pragma unroll
    for (int o = 512; o > 0; o >>= 1) {
        if (threadIdx.x < o) sm[threadIdx.x] = fmaxf(sm[threadIdx.x], sm[threadIdx.x + o]);
        __syncthreads();
    }
    if (threadIdx.x == 0) g_amax = fmaxf(sm[0], 1e-12f);
}

// ---------------- staging quant (x and w in one launch) --------------------------
__global__ void k_quant(const float* __restrict__ x, int nx4,
                        const float* __restrict__ w, int nw4) {
    float s = g_amax / FP8_MAX;
    int i = blockIdx.x * blockDim.x + threadIdx.x;
    int stride = gridDim.x * blockDim.x;
    const float4* x4 = (const float4*)x;
    uchar4* dx = (uchar4*)g_x_fp8;
    for (int j = i; j < nx4; j += stride) {
        float4 v = x4[j];
        uchar4 q;
        q.x = __nv_fp8_e4m3(bf16r(v.x) / s).__x;
        q.y = __nv_fp8_e4m3(bf16r(v.y) / s).__x;
        q.z = __nv_fp8_e4m3(bf16r(v.z) / s).__x;
        q.w = __nv_fp8_e4m3(bf16r(v.w) / s).__x;
        dx[j] = q;
    }
    const float4* w4 = (const float4*)w;
    uchar4* dw = (uchar4*)g_w_fp8;
    for (int j = i; j < nw4; j += stride) {
        float4 v = w4[j];
        uchar4 q;
        q.x = __nv_fp8_e4m3(v.x).__x;
        q.y = __nv_fp8_e4m3(v.y).__x;
        q.z = __nv_fp8_e4m3(v.z).__x;
        q.w = __nv_fp8_e4m3(v.w).__x;
        dw[j] = q;
    }
}

// ---- fp8 MMA GEMM: BK=32, 6 stages, barrier/2 iters, FULLY UNROLLED (K=1024) ---
#define BM 128
#define BN 128
#define BK 32                            // 32 fp8 bytes of K per stage
#define ROWB 48                          // 32 data + 16 pad (16B aligned rows)
#define OPB (128 * ROWB)                 // 6144 per operand tile
#define STB (2 * OPB)                    // 12288 per stage
#define STAGES 6
#define SMEM_GEMM_TOTAL (STAGES * STB)   // 73728 (needs attribute)
#define NKC 32                           // K/BK with K=1024 (fixed problem shape)

__global__ void __launch_bounds__(256, 2)   // <=128 regs -> 2 CTAs/SM, 1 wave
k_gemm(const float* __restrict__ wscale,
       const float* __restrict__ bias,
       float* __restrict__ out,          // f32 container, bf16-rounded values
       int M, int N, int K)
{
    extern __shared__ __align__(128) uint8_t smem[];
    const uint32_t sbase = smem_u32(smem);
    const int tid = threadIdx.x;
    const int wid = tid >> 5;
    const int lane = tid & 31;
    const int g = lane >> 2;             // groupID
    const int t = lane & 3;              // threadID_in_group
    const int wm = (wid & 3) * 32;       // 4 warps along M
    const int wn = (wid >> 2) * 64;      // 2 warps along N (warp tile 32x64)
    const int m0 = blockIdx.y * BM;
    const int n0 = blockIdx.x * BN;

    // ldmatrix lane offsets (validated fragment maps); fold into immediates
    const uint32_t la0 = sbase + (uint32_t)((wm + (lane & 15)) * ROWB + (lane >> 4) * 16);
    const uint32_t bo  = sbase + OPB + (uint32_t)(
        (wn + (lane & 7) + ((lane & 16) >> 1)) * ROWB + ((lane & 8) ? 16 : 0));

    // producer: each thread 1 16B piece of A + 1 of B per chunk
    const int prow = tid >> 1;
    const uint32_t apo = sbase + (uint32_t)(prow * ROWB + (tid & 1) * 16);
    const uint8_t* a_ptr = g_x_fp8 + (size_t)(m0 + prow) * K + (tid & 1) * 16;
    const uint8_t* b_ptr = g_w_fp8 + (size_t)(n0 + prow) * K + (tid & 1) * 16;

    float c[2][8][4];
#pragma unroll
    for (int i = 0; i < 2; i++)
#pragma unroll
        for (int j = 0; j < 8; j++)
#pragma unroll
            for (int q = 0; q < 4; q++) c[i][j][q] = 0.0f;

    // prologue: 4 chunks in flight (stages 0..3); all offsets compile-time
#pragma unroll
    for (int s = 0; s < 4; s++) {
        cp_async16(apo + (uint32_t)(s * STB), a_ptr + s * BK);
        cp_async16(apo + (uint32_t)(s * STB + OPB), b_ptr + s * BK);
        cp_commit();
    }

#pragma unroll
    for (int i = 0; i < NKC; i++) {      // i is a literal in every body
        cp_wait<3>();                    // chunk i resident (i+1..i+3 in flight)
        if ((i & 1) == 0) __syncthreads();  // write targets stage read at i-2

        if (i + 4 < NKC) {
            const uint32_t wst = (uint32_t)(((i + 4) % STAGES) * STB);
            cp_async16(apo + wst, a_ptr + (i + 4) * BK);
            cp_async16(apo + wst + OPB, b_ptr + (i + 4) * BK);
        }
        cp_commit();                     // unconditional: keeps wait counts valid

        const uint32_t rst = (uint32_t)((i % STAGES) * STB);

        uint32_t af[2][4];
        ldmatrix_x4(af[0], la0 + rst);
        ldmatrix_x4(af[1], la0 + rst + 16u * ROWB);
        uint32_t bf[4][4];
#pragma unroll
        for (int j = 0; j < 4; j++)
            ldmatrix_x4(bf[j], bo + rst + (uint32_t)(j * 16 * ROWB));

#pragma unroll
        for (int ti = 0; ti < 2; ti++)
#pragma unroll
            for (int j = 0; j < 4; j++) {
                mma_fp8(c[ti][2 * j],     af[ti], &bf[j][0]);
                mma_fp8(c[ti][2 * j + 1], af[ti], &bf[j][2]);
            }
    }

    // epilogue: f32 out, values rounded to bf16 grid (matches .astype(bf16))
    float act_scale = g_amax / FP8_MAX;
    const int row_b = m0 + wm + g;
    const int col_b = wn + 2 * t;
#pragma unroll
    for (int ti = 0; ti < 2; ti++) {
#pragma unroll
        for (int tj = 0; tj < 8; tj++) {
            int col = n0 + col_b + 8 * tj;
            float s0 = act_scale * __ldg(&wscale[col]);
            float s1 = act_scale * __ldg(&wscale[col + 1]);
            float b0 = __ldg(&bias[col]);
            float b1 = __ldg(&bias[col + 1]);
            int r0 = row_b + 16 * ti;
            int r1 = r0 + 8;
            float2 h0 = make_float2(bf16r(fmaf(c[ti][tj][0], s0, b0)),
                                    bf16r(fmaf(c[ti][tj][1], s1, b1)));
            float2 h1 = make_float2(bf16r(fmaf(c[ti][tj][2], s0, b0)),
                                    bf16r(fmaf(c[ti][tj][3], s1, b1)));
            *(float2*)(out + (size_t)r0 * N + col) = h0;
            *(float2*)(out + (size_t)r1 * N + col) = h1;
        }
    }
}

// ---------------- launch --------------------------------------------------------
extern "C" void kernel_launch(void* const* d_in, const int* in_sizes, int n_in,
                              void* d_out, int out_size) {
    const float* x  = (const float*)d_in[0];
    const float* w  = (const float*)d_in[1];
    const float* ws = (const float*)d_in[2];
    const float* b  = (const float*)d_in[3];
    float* out = (float*)d_out;                  // f32 container (numpy has no bf16)

    int d_out_dim = in_sizes[2];                 // 1024
    int d_in_dim  = in_sizes[1] / d_out_dim;     // 1024 (== NKC*BK)
    int tokens    = in_sizes[0] / d_in_dim;      // 32768
    int nx = in_sizes[0];
    int nw = in_sizes[1];

    // non-stream API, idempotent, legal during capture (R10/R13-verified)
    cudaFuncSetAttribute(k_gemm, cudaFuncAttributeMaxDynamicSharedMemorySize,
                         SMEM_GEMM_TOTAL);

    k_amax1<<<1024, 256>>>(x, nx);
    k_amax2<<<1, 1024>>>();
    k_quant<<<2048, 256>>>(x, nx >> 2, w, nw >> 2);

    dim3 grid(d_out_dim / BN, tokens / BM);      // N-tiles fastest -> A-tile L2 reuse
    k_gemm<<<grid, 256, SMEM_GEMM_TOTAL>>>(ws, b, out, tokens, d_out_dim, d_in_dim);
}